// round 17
// baseline (speedup 1.0000x reference)
#include <cuda_runtime.h>
#include <math.h>

#define BB 32
#define DD 1024
#define TXX 4096
#define WIN 4
#define NW 8
#define KC 64
#define GRID 296          // exactly 2 blocks per SM (148 SMs)
#define BLOCK 256

// Scratch (device globals; allocation forbidden).
// g_target / g_h are atomic accumulation buffers, zeroed in-kernel each launch.
// g_pt_part stays a fixed-order partial slab: the gather-index path must be
// order-deterministic; atomics there could flip an index.
__device__ float g_pt_part[16][BB][512];   // input @ W_p1^T partials (fixed order)
__device__ float g_target[BB * DD];        // input @ W_in^T   (atomic accum)
__device__ float g_h[BB * DD];             // cat @ W_out^T    (atomic accum)
__device__ float g_weighted[BB * DD];      // attn-weighted context

// Dataflow counters, one per 128B line; reset at kernel end -> replay-identical
__device__ volatile unsigned g_ctr[192];
#define CZ (g_ctr + 0)     // zero-fill done        (target 256)
#define CA (g_ctr + 32)    // A tiles accumulated   (target 128)
#define CB (g_ctr + 64)    // B tiles stored        (target 64)
#define CW (g_ctr + 96)    // weighted rows written (target 32)
#define CH (g_ctr + 128)   // h contributions done  (target 256 = 128 C + 128 G)
#define CD (g_ctr + 160)   // blocks finished       (target GRID)

__device__ __forceinline__ void ctr_inc(volatile unsigned* c) {
    __syncthreads();
    __threadfence();
    if (threadIdx.x == 0) atomicAdd((unsigned*)c, 1u);
}
__device__ __forceinline__ void ctr_wait(volatile unsigned* c, unsigned tgt) {
    if (threadIdx.x == 0) { while (*c < tgt) { } }
    __syncthreads();
    __threadfence();
}

// ---------------------------------------------------------------------------
// Tile: out[32, j0:+128] {=|+=} X[:, kx0:+64] * W[j, kw0:+64]^T  (256 threads)
// smem: Xs[64][36] at sm, Ws[64][132] at sm+2304 (43008B total)
__device__ __forceinline__ void loadW128(float* sm, const float* __restrict__ W,
                                         int wstride, int kw0, int j0)
{
    float (*Ws)[132] = (float (*)[132])(sm + 64 * 36);
    const int t = threadIdx.x;
    const float4* W4 = (const float4*)W;
#pragma unroll
    for (int i = t; i < 128 * 16; i += BLOCK) {
        int j = i >> 4, kq = i & 15;
        float4 v = W4[(size_t)(j0 + j) * (wstride >> 2) + (kw0 >> 2) + kq];
        Ws[kq * 4 + 0][j] = v.x; Ws[kq * 4 + 1][j] = v.y;
        Ws[kq * 4 + 2][j] = v.z; Ws[kq * 4 + 3][j] = v.w;
    }
}

__device__ __forceinline__ void loadX(float* sm, const float* __restrict__ X,
                                      int xstride, int kx0)
{
    float (*Xs)[36] = (float (*)[36])sm;
    const int t = threadIdx.x;
    const float4* X4 = (const float4*)X;
#pragma unroll
    for (int i = t; i < 32 * 16; i += BLOCK) {
        int b = i >> 4, kq = i & 15;
        float4 v = X4[(size_t)b * (xstride >> 2) + (kx0 >> 2) + kq];
        Xs[kq * 4 + 0][b] = v.x; Xs[kq * 4 + 1][b] = v.y;
        Xs[kq * 4 + 2][b] = v.z; Xs[kq * 4 + 3][b] = v.w;
    }
}

template <int ATOMIC>
__device__ void compute128(float* sm, float* __restrict__ out, int ostride, int j0)
{
    float (*Xs)[36]  = (float (*)[36])sm;
    float (*Ws)[132] = (float (*)[132])(sm + 64 * 36);
    const int t  = threadIdx.x;
    const int tb = t & 7;
    const int tj = t >> 3;

    float acc[4][4];
#pragma unroll
    for (int i = 0; i < 4; i++)
#pragma unroll
        for (int j = 0; j < 4; j++) acc[i][j] = 0.f;

#pragma unroll 16
    for (int k = 0; k < KC; k++) {
        float4 x = *(const float4*)&Xs[k][tb * 4];
        float4 w = *(const float4*)&Ws[k][tj * 4];
        acc[0][0] += x.x * w.x; acc[0][1] += x.x * w.y; acc[0][2] += x.x * w.z; acc[0][3] += x.x * w.w;
        acc[1][0] += x.y * w.x; acc[1][1] += x.y * w.y; acc[1][2] += x.y * w.z; acc[1][3] += x.y * w.w;
        acc[2][0] += x.z * w.x; acc[2][1] += x.z * w.y; acc[2][2] += x.z * w.z; acc[2][3] += x.z * w.w;
        acc[3][0] += x.w * w.x; acc[3][1] += x.w * w.y; acc[3][2] += x.w * w.z; acc[3][3] += x.w * w.w;
    }

#pragma unroll
    for (int i = 0; i < 4; i++) {
        if (ATOMIC) {
#pragma unroll
            for (int jj = 0; jj < 4; jj++)
                atomicAdd(&out[(size_t)(tb * 4 + i) * ostride + j0 + tj * 4 + jj],
                          acc[i][jj]);
        } else {
            float4 v = make_float4(acc[i][0], acc[i][1], acc[i][2], acc[i][3]);
            *(float4*)&out[(size_t)(tb * 4 + i) * ostride + j0 + tj * 4] = v;
        }
    }
}

template <int ATOMIC>
__device__ void gemm_j128(float* sm,
                          const float* __restrict__ X, int xstride, int kx0,
                          const float* __restrict__ W, int wstride, int kw0,
                          float* __restrict__ out, int ostride, int j0)
{
    __syncthreads();                 // previous smem user done
    loadX(sm, X, xstride, kx0);
    loadW128(sm, W, wstride, kw0, j0);
    __syncthreads();
    compute128<ATOMIC>(sm, out, ostride, j0);
}

// ---------------------------------------------------------------------------
__global__ void __launch_bounds__(BLOCK, 3)
k_all(const float* __restrict__ input,
      const float* __restrict__ context,
      const float* __restrict__ W_in,
      const float* __restrict__ W_p1,
      const float* __restrict__ W_p2,
      const float* __restrict__ W_out,
      float* __restrict__ out) {
    __shared__ __align__(16) float s_raw[10752];  // 43008B
    __shared__ float s_red[4], s_part[NW], s_attn[NW];
    __shared__ int   s_idx[NW];

    const int r = blockIdx.x;
    const int t = threadIdx.x;
    const int warp = t >> 5, lane = t & 31;

    // ==== Stage 0: zero the atomic accumulators ====
    if (r < 128)      g_target[r * BLOCK + t] = 0.f;
    else if (r < 256) g_h[(r - 128) * BLOCK + t] = 0.f;
    if (r < 256) ctr_inc(CZ);

    // ==== Stage 1: input-dependent GEMM tiles ====
    if (r < 128) {                       // A: W_in (8jt x 16kt) -> g_target
        int jt = r & 7, kt = r >> 3;
        ctr_wait(CZ, 256);
        gemm_j128<1>(s_raw, input, DD, kt * KC, W_in, DD, kt * KC,
                     g_target, DD, jt * 128);
        ctr_inc(CA);
    } else if (r < 192) {                // B: W_p1 (4jt x 16kt), fixed-order slab
        int bi = r - 128, jt = bi & 3, kt = bi >> 2;
        gemm_j128<0>(s_raw, input, DD, kt * KC, W_p1, DD, kt * KC,
                     &g_pt_part[kt][0][0], 512, jt * 128);
        ctr_inc(CB);
    } else {                             // C: W_out upper half -> g_h (atomic)
        int ci = r - 192;                // tiles 0..103, then 104..127
        ctr_wait(CZ, 256);
        {
            int jt = ci & 7, kt = ci >> 3;
            gemm_j128<1>(s_raw, input, DD, kt * KC, W_out, 2 * DD, DD + kt * KC,
                         g_h, DD, jt * 128);
            ctr_inc(CH);
        }
        if (ci < 24) {
            int c2 = ci + 104, jt = c2 & 7, kt = c2 >> 3;
            gemm_j128<1>(s_raw, input, DD, kt * KC, W_out, 2 * DD, DD + kt * KC,
                         g_h, DD, jt * 128);
            ctr_inc(CH);
        }
    }

    // ==== Stage 2 ====
    if (r < BB) {
        // ---- attention, one block per batch ----
        const int b = r;
        float (*s_cw)[DD] = (float (*)[DD])s_raw;   // 8 x 1024
        float* s_t = s_raw + NW * DD;               // 1024

        // pt score: fixed-order reduce of B partials (index path — deterministic)
        ctr_wait(CB, 64);
        if (t < 128) {
            float4 v = make_float4(0.f, 0.f, 0.f, 0.f);
#pragma unroll
            for (int p = 0; p < 16; p++) {
                float4 u = ((const float4*)&g_pt_part[p][b][0])[t];
                v.x += u.x; v.y += u.y; v.z += u.z; v.w += u.w;
            }
            float4 w = ((const float4*)W_p2)[t];
            float local = tanhf(v.x) * w.x + tanhf(v.y) * w.y
                        + tanhf(v.z) * w.z + tanhf(v.w) * w.w;
#pragma unroll
            for (int o = 16; o; o >>= 1) local += __shfl_xor_sync(0xffffffffu, local, o);
            if (lane == 0) s_red[warp] = local;
        }
        __syncthreads();

        if (t == 0) {
            float s = s_red[0] + s_red[1] + s_red[2] + s_red[3];
            float pt2 = (float)TXX * (1.f / (1.f + expf(-s)));
            int bl = (int)truncf(pt2 - (float)WIN);   // jnp.trunc -> int32
#pragma unroll
            for (int w = 0; w < NW; w++) {
                int id = bl + w;
                id = id < 0 ? 0 : (id > TXX - 1 ? TXX - 1 : id);
                s_idx[w] = id;
            }
        }
        __syncthreads();

        // gather (DRAM-cold) issued BEFORE waiting on A accumulation
        {
            const float4* crow =
                (const float4*)&context[((size_t)b * TXX + s_idx[warp]) * DD];
            float4* dst = (float4*)&s_cw[warp][0];
#pragma unroll
            for (int i = lane; i < 256; i += 32) dst[i] = crow[i];
        }

        // target row: direct read of accumulated g_target (1 float4/thread)
        ctr_wait(CA, 128);
        ((float4*)s_t)[t] = ((const float4*)&g_target[b * DD])[t];
        __syncthreads();

        // scores: one warp per row
        {
            const float4* c4 = (const float4*)&s_cw[warp][0];
            const float4* t4 = (const float4*)s_t;
            float p = 0.f;
#pragma unroll
            for (int i = lane; i < 256; i += 32) {
                float4 c = c4[i], x = t4[i];
                p += c.x * x.x + c.y * x.y + c.z * x.z + c.w * x.w;
            }
#pragma unroll
            for (int o = 16; o; o >>= 1) p += __shfl_xor_sync(0xffffffffu, p, o);
            if (lane == 0) s_part[warp] = p;
        }
        __syncthreads();

        // softmax over 8 (+ attn output)
        if (t == 0) {
            float m = -1e30f;
#pragma unroll
            for (int w = 0; w < NW; w++) m = fmaxf(m, s_part[w]);
            float e[NW], sum = 0.f;
#pragma unroll
            for (int w = 0; w < NW; w++) { e[w] = expf(s_part[w] - m); sum += e[w]; }
            float inv = 1.f / sum;
#pragma unroll
            for (int w = 0; w < NW; w++) {
                float a = e[w] * inv;
                s_attn[w] = a;
                out[BB * DD + b * NW + w] = a;
            }
        }
        __syncthreads();

        // weighted[b,:] = sum_w attn[w] * cw[w,:]
        {
            float4 acc = make_float4(0.f, 0.f, 0.f, 0.f);
#pragma unroll
            for (int w = 0; w < NW; w++) {
                float a = s_attn[w];
                float4 c = ((const float4*)&s_cw[w][0])[t];
                acc.x += a * c.x; acc.y += a * c.y; acc.z += a * c.z; acc.w += a * c.w;
            }
            ((float4*)&g_weighted[b * DD])[t] = acc;
        }
        ctr_inc(CW);
    } else if (r < 160) {
        // ---- G: weighted-half W_out tiles -> g_h (atomic), blocks 32..159 ----
        // Prefetch W tile into smem BEFORE the dependency wait (runs during attn)
        int gi = r - 32, jt = gi & 7, kt = gi >> 3;
        __syncthreads();   // stage-1 smem reads done
        loadW128(s_raw, W_out, 2 * DD, kt * KC, jt * 128);
        ctr_wait(CW, BB);  // transitively guarantees CZ done as well
        loadX(s_raw, g_weighted, DD, kt * KC);
        __syncthreads();
        compute128<1>(s_raw, g_h, DD, jt * 128);
        ctr_inc(CH);
    }
    // blocks 160..191: done after their B tile

    // ==== Stage 3: final tanh on blocks 0..127 ====
    if (r < 128) {
        ctr_wait(CH, 256);
        int i = r * BLOCK + t;           // [0, 32768)
        out[i] = tanhf(g_h[i]);
    }

    // ==== Reset counters for next (identical) replay ====
    __syncthreads();
    if (t == 0) {
        unsigned d = atomicAdd((unsigned*)CD, 1u) + 1u;
        if (d == GRID) {
            *(unsigned*)CZ = 0u; *(unsigned*)CA = 0u; *(unsigned*)CB = 0u;
            *(unsigned*)CW = 0u; *(unsigned*)CH = 0u; *(unsigned*)CD = 0u;
            __threadfence();
        }
    }
}

// ---------------------------------------------------------------------------
extern "C" void kernel_launch(void* const* d_in, const int* in_sizes, int n_in,
                              void* d_out, int out_size) {
    const float *input = 0, *context = 0, *W_in = 0, *W_out = 0, *W_p1 = 0, *W_p2 = 0;
    for (int i = 0; i < n_in; i++) {
        switch (in_sizes[i]) {
            case BB * DD:       input   = (const float*)d_in[i]; break;
            case BB * TXX * DD: context = (const float*)d_in[i]; break;
            case DD * DD:       W_in    = (const float*)d_in[i]; break;
            case DD * 2 * DD:   W_out   = (const float*)d_in[i]; break;
            case 512 * DD:      W_p1    = (const float*)d_in[i]; break;
            case 512:           W_p2    = (const float*)d_in[i]; break;
        }
    }
    k_all<<<GRID, BLOCK>>>(input, context, W_in, W_p1, W_p2, W_out, (float*)d_out);
}